// round 9
// baseline (speedup 1.0000x reference)
#include <cuda_runtime.h>
#include <math.h>
#include <stdint.h>

#define TT   4096
#define HID  2048
#define NH   32
#define HD   128
#define PP   4096
#define TP   (TT * PP)
#define NMEGA 12672   // qkv(12288) | fa(128) | ga(128) | beta(32 pad->384 total)
#define FABOFF 12288

// ---------------- scratch (device globals; no allocations allowed) ----------
__device__ float g_hsr[TT * HID];
__device__ float g_qkvfab[TT * NMEGA];
__device__ float g_q [TP];
__device__ float g_k [TP];
__device__ float g_v [TP];
__device__ float g_eg[TP];
__device__ float g_g2[TP];
__device__ float g_o [TP];
__device__ float g_beta[TT * NH];
__device__ float g_wmegaR[HID * NMEGA];
__device__ float g_wfbR[HD * PP];
__device__ float g_wgbR[HD * PP];
__device__ float g_woR[PP * HID];

// ---------------- helpers -----------------------------------------------------
__device__ __forceinline__ uint32_t smem_u32(const void* p) {
    uint32_t a;
    asm("{ .reg .u64 t; cvta.to.shared.u64 t, %1; cvt.u32.u64 %0, t; }" : "=r"(a) : "l"(p));
    return a;
}
__device__ __forceinline__ float rna_tf32(float x) {
    uint32_t o, i = __float_as_uint(x);
    asm("cvt.rna.tf32.f32 %0, %1;" : "=r"(o) : "r"(i));
    return __uint_as_float(o);
}
__device__ __forceinline__ void cp_async16(uint32_t dst, const float* src) {
    asm volatile("cp.async.cg.shared.global [%0], [%1], 16;\n"
                 :: "r"(dst), "l"(__cvta_generic_to_global(src)));
}
__device__ __forceinline__ void cp_async4(uint32_t dst, const float* src) {
    asm volatile("cp.async.ca.shared.global [%0], [%1], 4;\n"
                 :: "r"(dst), "l"(__cvta_generic_to_global(src)));
}
__device__ __forceinline__ void cp_commit() { asm volatile("cp.async.commit_group;\n" ::: "memory"); }

#define MMA_TF32(d, a, b)                                                      \
    asm volatile("mma.sync.aligned.m16n8k8.row.col.f32.tf32.tf32.f32 "        \
                 "{%0,%1,%2,%3}, {%4,%5,%6,%7}, {%8,%9}, {%0,%1,%2,%3};"      \
                 : "+f"((d)[0]), "+f"((d)[1]), "+f"((d)[2]), "+f"((d)[3])     \
                 : "r"((a)[0]), "r"((a)[1]), "r"((a)[2]), "r"((a)[3]),        \
                   "r"((b)[0]), "r"((b)[1]))

#define LDSM_X4(r, addr)                                                       \
    asm volatile("ldmatrix.sync.aligned.m8n8.x4.shared.b16 {%0,%1,%2,%3}, [%4];" \
                 : "=r"((r)[0]), "=r"((r)[1]), "=r"((r)[2]), "=r"((r)[3])      \
                 : "r"(addr))

// ---------------- tf32 mma.sync GEMM body (R7/R8 proven) ----------------------
#define BM 128
#define BN 128
#define BK 32
#define ASTR 36
#define BSTR 136
#define A_STAGE (BM * ASTR)
#define B_STAGE (BK * BSTR)
#define STAGE_F (A_STAGE + B_STAGE)
#define NSTAGE 3
#define GEMM_SMEM (NSTAGE * STAGE_F * 4)

// mode 1: round cols in [round_lo, round_hi); mode 2: KDA gate epilogue
__device__ __forceinline__ void gemm_body(const float* __restrict__ A, int lda,
                                          const float* __restrict__ B, int ldb,
                                          float* __restrict__ C, int ldc,
                                          int Nvalid, int K, int bm, int bn,
                                          int mode, int round_lo, int round_hi,
                                          const float* __restrict__ dtb,
                                          const float* __restrict__ Alog) {
    extern __shared__ float sm[];
    const uint32_t sb = smem_u32(sm);

    const int tid = threadIdx.x;
    const int wid = tid >> 5, lane = tid & 31;
    const int g = lane >> 2, tig = lane & 3;
    const int wm = (wid & 1) * 64, wn = (wid >> 1) * 32;
    const int NC = K >> 5;

    const int arow = tid >> 3, akq = tid & 7;
    const int brow = tid >> 5, bnq = tid & 31;
    const int aoff = (wm + (lane & 7) + ((lane >> 3) & 1) * 8) * ASTR + (lane >> 4) * 4;

    float acc[4][4][4];
#pragma unroll
    for (int i = 0; i < 4; i++)
#pragma unroll
        for (int j = 0; j < 4; j++)
#pragma unroll
            for (int r = 0; r < 4; r++) acc[i][j][r] = 0.f;

#define LOADST(chunk, stage) do {                                               \
        const int kb = (chunk) * BK;                                            \
        const uint32_t sA = sb + (stage) * STAGE_F * 4;                         \
        const uint32_t sB = sA + A_STAGE * 4;                                   \
        _Pragma("unroll")                                                       \
        for (int j = 0; j < 4; j++) {                                           \
            const int r = arow + 32 * j;                                        \
            cp_async16(sA + (r * ASTR + akq * 4) * 4,                           \
                       A + (size_t)(bm + r) * lda + kb + akq * 4);              \
        }                                                                       \
        _Pragma("unroll")                                                       \
        for (int j = 0; j < 4; j++) {                                           \
            const int r = brow + 8 * j;                                         \
            cp_async16(sB + (r * BSTR + bnq * 4) * 4,                           \
                       B + (size_t)(kb + r) * ldb + bn + bnq * 4);              \
        }                                                                       \
        cp_commit();                                                            \
    } while (0)

    LOADST(0, 0);
    if (NC > 1) LOADST(1, 1);

    for (int i = 0; i < NC; i++) {
        if (i + 2 < NC) asm volatile("cp.async.wait_group 1;\n" ::: "memory");
        else            asm volatile("cp.async.wait_group 0;\n" ::: "memory");
        __syncthreads();
        if (i + 2 < NC) {
            int st = i + 2;
            st = st - (st / NSTAGE) * NSTAGE;
            LOADST(i + 2, st);
        }

        const int stage = i - (i / NSTAGE) * NSTAGE;
        const uint32_t aBase = sb + stage * (STAGE_F * 4);
        const float* bb = sm + stage * STAGE_F + A_STAGE;
#pragma unroll
        for (int s = 0; s < 4; s++) {
            uint32_t af[4][4], bf[4][2];
            const int kk = 8 * s + tig;
#pragma unroll
            for (int mf = 0; mf < 4; mf++)
                LDSM_X4(af[mf], aBase + (uint32_t)(aoff + mf * (16 * ASTR) + 8 * s) * 4);
            const float* brow0 = bb + kk * BSTR + wn;
#pragma unroll
            for (int nf = 0; nf < 4; nf++) {
                bf[nf][0] = __float_as_uint(brow0[8 * nf + g]);
                bf[nf][1] = __float_as_uint(brow0[8 * nf + g + 4 * BSTR]);
            }
#pragma unroll
            for (int mf = 0; mf < 4; mf++)
#pragma unroll
                for (int nf = 0; nf < 4; nf++)
                    MMA_TF32(acc[mf][nf], af[mf], bf[nf]);
        }
        __syncthreads();
    }

#pragma unroll
    for (int mf = 0; mf < 4; mf++) {
        const int row0 = bm + wm + 16 * mf + g;
#pragma unroll
        for (int nf = 0; nf < 4; nf++) {
            const int col = bn + wn + 8 * nf + 2 * tig;
            if (col < Nvalid) {
                float4 vals = make_float4(acc[mf][nf][0], acc[mf][nf][1],
                                          acc[mf][nf][2], acc[mf][nf][3]);
                if (mode == 1) {
                    if (col >= round_lo && col < round_hi) {
                        vals.x = rna_tf32(vals.x); vals.y = rna_tf32(vals.y);
                        vals.z = rna_tf32(vals.z); vals.w = rna_tf32(vals.w);
                    }
                } else if (mode == 2) {
                    const float a = expf(Alog[col >> 7]);
                    const float d0 = dtb[col], d1 = dtb[col + 1];
                    float sg;
                    sg = 1.f / (1.f + expf(-a * (vals.x + d0))); vals.x = expf(-5.f * sg);
                    sg = 1.f / (1.f + expf(-a * (vals.y + d1))); vals.y = expf(-5.f * sg);
                    sg = 1.f / (1.f + expf(-a * (vals.z + d0))); vals.z = expf(-5.f * sg);
                    sg = 1.f / (1.f + expf(-a * (vals.w + d1))); vals.w = expf(-5.f * sg);
                }
                *reinterpret_cast<float2*>(C + (size_t)row0 * ldc + col) =
                    make_float2(vals.x, vals.y);
                *reinterpret_cast<float2*>(C + (size_t)(row0 + 8) * ldc + col) =
                    make_float2(vals.z, vals.w);
            }
        }
    }
}

__global__ __launch_bounds__(256, 2) void mma_gemm(const float* __restrict__ A, int lda,
                                                   const float* __restrict__ B, int ldb,
                                                   float* __restrict__ C, int ldc,
                                                   int Nvalid, int K,
                                                   int round_lo, int round_hi) {
    gemm_body(A, lda, B, ldb, C, ldc, Nvalid, K,
              blockIdx.y * BM, blockIdx.x * BN, 1, round_lo, round_hi, 0, 0);
}

// ---------------- fused mid stage: eg-GEMM(+gate) | g2-GEMM | convs | beta ----
#define CONV_BLKS 65536
#define FUSED_GRID (2048 + 3 * CONV_BLKS + 512)

__global__ __launch_bounds__(256, 2) void fused_mid(
    const float* __restrict__ qkvfab,
    const float* __restrict__ wfb, const float* __restrict__ wgb,
    float* __restrict__ eg, float* __restrict__ g2,
    float* __restrict__ q, float* __restrict__ k, float* __restrict__ v,
    float* __restrict__ beta,
    const float* __restrict__ cq, const float* __restrict__ ck,
    const float* __restrict__ cv,
    const float* __restrict__ dtb, const float* __restrict__ Alog) {
    const int bx = blockIdx.x;
    if (bx < 2048) {
        const int which = bx >> 10, t = bx & 1023;
        const int bn = (t & 31) * BN, bm = (t >> 5) * BM;
        if (which == 0)
            gemm_body(qkvfab + FABOFF, NMEGA, wfb, PP, eg, PP, PP, HD,
                      bm, bn, 2, 0, 0, dtb, Alog);
        else
            gemm_body(qkvfab + FABOFF + 128, NMEGA, wgb, PP, g2, PP, PP, HD,
                      bm, bn, 1, 0, 0, 0, 0);
        return;
    }
    int r = bx - 2048;
    if (r < 3 * CONV_BLKS) {
        const int tensor = r >> 16;
        const int idx = ((r & (CONV_BLKS - 1)) << 8) + threadIdx.x;
        const int t = idx >> 12, p = idx & (PP - 1);
        const float* cw = tensor == 0 ? cq : (tensor == 1 ? ck : cv);
        float* dst = tensor == 0 ? q : (tensor == 1 ? k : v);
        const float scale = tensor == 0 ? 0.08838834764831845f : 1.f;
        const size_t xi = (size_t)t * NMEGA + tensor * PP + p;
        const float4 wv4 = *reinterpret_cast<const float4*>(cw + p * 4);
        float acc = qkvfab[xi] * wv4.w;
        if (t >= 1) acc += qkvfab[xi - NMEGA] * wv4.z;
        if (t >= 2) acc += qkvfab[xi - 2 * NMEGA] * wv4.y;
        if (t >= 3) acc += qkvfab[xi - 3 * NMEGA] * wv4.x;
        const float sg = 1.f / (1.f + expf(-acc));
        dst[idx] = acc * sg * scale;
        return;
    }
    r -= 3 * CONV_BLKS;
    const int idx = (r << 8) + threadIdx.x;
    if (idx < TT * NH) {
        const int t = idx >> 5, h = idx & 31;
        const float x = qkvfab[(size_t)t * NMEGA + FABOFF + 256 + h];
        beta[idx] = 2.f / (1.f + expf(-x));
    }
}

// ---------------- prep_all: every tf32-rounded copy in one launch -------------
#define PREP_N0 (TT * HID / 4)
#define PREP_N1 (HID * NMEGA / 4)
#define PREP_N2 (HD * PP / 4)
#define PREP_N4 (PP * HID / 4)
#define PREP_TOTAL (PREP_N0 + PREP_N1 + 2 * PREP_N2 + PREP_N4)

__global__ void prep_all(const float4* __restrict__ hs,
                         const float4* __restrict__ wq, const float4* __restrict__ wk,
                         const float4* __restrict__ wv, const float4* __restrict__ wfa,
                         const float4* __restrict__ wga, const float4* __restrict__ wb,
                         const float4* __restrict__ wfb, const float4* __restrict__ wgb,
                         const float4* __restrict__ wo,
                         float4* __restrict__ hsr, float4* __restrict__ wmega,
                         float4* __restrict__ wfbR, float4* __restrict__ wgbR,
                         float4* __restrict__ woR) {
    const int i = blockIdx.x * 256 + threadIdx.x;
    if (i >= PREP_TOTAL) return;
    float4 vv;
    float4* dst;
    if (i < PREP_N0) {
        vv = hs[i]; dst = hsr + i;
    } else if (i < PREP_N0 + PREP_N1) {
        const int j = i - PREP_N0;
        const int row = j / (NMEGA / 4);
        const int c4 = j - row * (NMEGA / 4);
        if (c4 < 3072) {
            const int seg = c4 >> 10;
            const int off = row * 1024 + (c4 & 1023);
            vv = (seg == 0) ? wq[off] : (seg == 1) ? wk[off] : wv[off];
        } else {
            const int f = c4 - 3072;
            if (f < 32)       vv = wfa[row * 32 + f];
            else if (f < 64)  vv = wga[row * 32 + (f - 32)];
            else if (f < 72)  vv = wb[row * 8 + (f - 64)];
            else              vv = make_float4(0.f, 0.f, 0.f, 0.f);
        }
        dst = wmega + j;
    } else if (i < PREP_N0 + PREP_N1 + PREP_N2) {
        const int j = i - PREP_N0 - PREP_N1;
        vv = wfb[j]; dst = wfbR + j;
    } else if (i < PREP_N0 + PREP_N1 + 2 * PREP_N2) {
        const int j = i - PREP_N0 - PREP_N1 - PREP_N2;
        vv = wgb[j]; dst = wgbR + j;
    } else {
        const int j = i - PREP_N0 - PREP_N1 - 2 * PREP_N2;
        vv = wo[j]; dst = woR + j;
    }
    vv.x = rna_tf32(vv.x); vv.y = rna_tf32(vv.y);
    vv.z = rna_tf32(vv.z); vv.w = rna_tf32(vv.w);
    *dst = vv;
}

// ---------------- KDA scan (unchanged from R8 — clean profiling target) -------
#define SBLK 8
#define SLOT_F 420
#define BUF_F (SBLK * SLOT_F)
#define SNBUF 3
#define NBLK (TT / SBLK)

__global__ __launch_bounds__(256) void scan_k(const float* __restrict__ q,
                                              const float* __restrict__ k,
                                              const float* __restrict__ v,
                                              const float* __restrict__ eg,
                                              const float* __restrict__ beta,
                                              float* __restrict__ o) {
    __shared__ float ring[SNBUF * BUF_F];

    const int tid = threadIdx.x;
    const int h = blockIdx.y;
    const int jb = blockIdx.x;
    const int jl = tid >> 3;
    const int s = tid & 7;
    const int off_v = h * HD + jb * 32 + jl;
    const uint32_t ring_u32 = smem_u32(ring);

    const float* kqe_base[3] = {k + h * HD, q + h * HD, eg + h * HD};

#define SCAN_FILL(blk) do {                                                     \
        const int t0 = (blk) * SBLK;                                            \
        const uint32_t bufb = ring_u32 + ((blk) % SNBUF) * (BUF_F * 4);         \
        for (int u = tid; u < SBLK * 104; u += 256) {                           \
            const int st = u / 104;                                             \
            const int item = u - st * 104;                                      \
            const size_t gbase = (size_t)(t0 + st) * PP;                        \
            const float* src;                                                   \
            if (item < 96) src = kqe_base[item >> 5] + gbase + (item & 31) * 4; \
            else           src = v + gbase + h * HD + jb * 32 + (item - 96) * 4;\
            cp_async16(bufb + (st * SLOT_F + item * 4) * 4, src);               \
        }                                                                       \
        if (tid < SBLK)                                                         \
            cp_async4(bufb + (tid * SLOT_F + 416) * 4,                          \
                      beta + (size_t)(t0 + tid) * NH + h);                      \
        cp_commit();                                                            \
    } while (0)

    float S[16];
#pragma unroll
    for (int r = 0; r < 16; r++) S[r] = 0.f;

    SCAN_FILL(0);
    SCAN_FILL(1);

    for (int b = 0; b < NBLK; b++) {
        if (b < NBLK - 1) asm volatile("cp.async.wait_group 1;\n" ::: "memory");
        else              asm volatile("cp.async.wait_group 0;\n" ::: "memory");
        __syncthreads();
        if (b + 2 < NBLK) SCAN_FILL(b + 2);

        const float* buf = ring + (b % SNBUF) * BUF_F;
#pragma unroll
        for (int si = 0; si < SBLK; si++) {
            const float* slot = buf + si * SLOT_F;
            const float* kp = slot + s * 16;
            const float* qp = slot + 128 + s * 16;
            const float* ep = slot + 256 + s * 16;
            float kf[16], qf[16], ef[16];
#pragma unroll
            for (int r = 0; r < 16; r += 4) {
                float4 kv4 = *reinterpret_cast<const float4*>(kp + r);
                float4 qv4 = *reinterpret_cast<const float4*>(qp + r);
                float4 ev4 = *reinterpret_cast<const float4*>(ep + r);
                kf[r] = kv4.x; kf[r+1] = kv4.y; kf[r+2] = kv4.z; kf[r+3] = kv4.w;
                qf[r] = qv4.x; qf[r+1] = qv4.y; qf[r+2] = qv4.z; qf[r+3] = qv4.w;
                ef[r] = ev4.x; ef[r+1] = ev4.y; ef[r+2] = ev4.z; ef[r+3] = ev4.w;
            }
            const float vt = slot[384 + jl];
            const float bt = slot[416];

            float p0 = 0.f, p1 = 0.f;
#pragma unroll
            for (int r = 0; r < 16; r += 2) {
                S[r]     *= ef[r];     p0 += S[r]     * kf[r];
                S[r + 1] *= ef[r + 1]; p1 += S[r + 1] * kf[r + 1];
            }
            float part = p0 + p1;
            part += __shfl_xor_sync(0xffffffffu, part, 1);
            part += __shfl_xor_sync(0xffffffffu, part, 2);
            part += __shfl_xor_sync(0xffffffffu, part, 4);
            const float u = bt * (vt - part);
            float o0 = 0.f, o1 = 0.f;
#pragma unroll
            for (int r = 0; r < 16; r += 2) {
                S[r]     += kf[r] * u;     o0 += qf[r]     * S[r];
                S[r + 1] += kf[r + 1] * u; o1 += qf[r + 1] * S[r + 1];
            }
            float po = o0 + o1;
            po += __shfl_xor_sync(0xffffffffu, po, 1);
            po += __shfl_xor_sync(0xffffffffu, po, 2);
            po += __shfl_xor_sync(0xffffffffu, po, 4);
            if (s == 0) o[(size_t)(b * SBLK + si) * PP + off_v] = po;
        }
        __syncthreads();
    }
}

// ---------------- gated RMSNorm (rounds output for Wo GEMM) -------------------
__global__ __launch_bounds__(256) void rmsnorm_k(float* __restrict__ o,
                                                 const float* __restrict__ g2,
                                                 const float* __restrict__ w) {
    const int warp = (blockIdx.x * blockDim.x + threadIdx.x) >> 5;
    const int lane = threadIdx.x & 31;
    if (warp >= TT * NH) return;
    const int base = warp * HD + lane * 4;
    float4 x = *reinterpret_cast<const float4*>(o + base);
    float ss = x.x * x.x + x.y * x.y + x.z * x.z + x.w * x.w;
#pragma unroll
    for (int d = 16; d > 0; d >>= 1) ss += __shfl_xor_sync(0xffffffffu, ss, d);
    const float rstd = rsqrtf(ss * (1.f / 128.f) + 1e-5f);
    const float4 g = *reinterpret_cast<const float4*>(g2 + base);
    const float4 wv = *reinterpret_cast<const float4*>(w + lane * 4);
    float4 r;
    r.x = rna_tf32(x.x * rstd * wv.x / (1.f + expf(-g.x)));
    r.y = rna_tf32(x.y * rstd * wv.y / (1.f + expf(-g.y)));
    r.z = rna_tf32(x.z * rstd * wv.z / (1.f + expf(-g.z)));
    r.w = rna_tf32(x.w * rstd * wv.w / (1.f + expf(-g.w)));
    *reinterpret_cast<float4*>(o + base) = r;
}

// ---------------- launch --------------------------------------------------------
extern "C" void kernel_launch(void* const* d_in, const int* in_sizes, int n_in,
                              void* d_out, int out_size) {
    const float* hs   = (const float*)d_in[0];
    const float* Wq   = (const float*)d_in[1];
    const float* Wk   = (const float*)d_in[2];
    const float* Wv   = (const float*)d_in[3];
    const float* cq   = (const float*)d_in[4];
    const float* ck   = (const float*)d_in[5];
    const float* cv   = (const float*)d_in[6];
    const float* Wb   = (const float*)d_in[7];
    const float* Wfa  = (const float*)d_in[8];
    const float* Wfb  = (const float*)d_in[9];
    const float* dtb  = (const float*)d_in[10];
    const float* Alog = (const float*)d_in[11];
    const float* Wga  = (const float*)d_in[12];
    const float* Wgb  = (const float*)d_in[13];
    const float* onw  = (const float*)d_in[14];
    const float* Wo   = (const float*)d_in[15];
    float* out = (float*)d_out;

    float *hsr, *qkvfab, *q, *k, *v, *eg, *g2, *o, *beta;
    float *wmegaR, *wfbR, *wgbR, *woR;
    cudaGetSymbolAddress((void**)&hsr, g_hsr);
    cudaGetSymbolAddress((void**)&qkvfab, g_qkvfab);
    cudaGetSymbolAddress((void**)&q,  g_q);
    cudaGetSymbolAddress((void**)&k,  g_k);
    cudaGetSymbolAddress((void**)&v,  g_v);
    cudaGetSymbolAddress((void**)&eg, g_eg);
    cudaGetSymbolAddress((void**)&g2, g_g2);
    cudaGetSymbolAddress((void**)&o,  g_o);
    cudaGetSymbolAddress((void**)&beta, g_beta);
    cudaGetSymbolAddress((void**)&wmegaR, g_wmegaR);
    cudaGetSymbolAddress((void**)&wfbR, g_wfbR);
    cudaGetSymbolAddress((void**)&wgbR, g_wgbR);
    cudaGetSymbolAddress((void**)&woR, g_woR);

    cudaFuncSetAttribute(mma_gemm, cudaFuncAttributeMaxDynamicSharedMemorySize, GEMM_SMEM);
    cudaFuncSetAttribute(fused_mid, cudaFuncAttributeMaxDynamicSharedMemorySize, GEMM_SMEM);

    const dim3 blk(256);

    // 0: all rounded-weight prep in one launch
    prep_all<<<(PREP_TOTAL + 255) / 256, blk>>>(
        (const float4*)hs, (const float4*)Wq, (const float4*)Wk, (const float4*)Wv,
        (const float4*)Wfa, (const float4*)Wga, (const float4*)Wb,
        (const float4*)Wfb, (const float4*)Wgb, (const float4*)Wo,
        (float4*)hsr, (float4*)wmegaR, (float4*)wfbR, (float4*)wgbR, (float4*)woR);

    // 1: mega GEMM -> qkv | fa | ga | beta_raw (fa/ga tf32-rounded in epilogue)
    mma_gemm<<<dim3(NMEGA / BN, TT / BM), blk, GEMM_SMEM>>>(
        hsr, HID, wmegaR, NMEGA, qkvfab, NMEGA, NMEGA, HID, FABOFF, FABOFF + 256);

    // 2: fused mid: eg GEMM (gate epilogue) + g2 GEMM + 3 convs + beta
    fused_mid<<<FUSED_GRID, blk, GEMM_SMEM>>>(qkvfab, wfbR, wgbR, eg, g2,
                                              q, k, v, beta, cq, ck, cv, dtb, Alog);

    // 3: sequential KDA scan (PROFILED LAUNCH)
    scan_k<<<dim3(4, NH), blk>>>(q, k, v, eg, beta, o);

    // 4: gated rmsnorm (rounds o)
    rmsnorm_k<<<(TT * NH * 32) / 256, blk>>>(o, g2, onw);

    // 5: output projection
    mma_gemm<<<dim3(HID / BN, TT / BM), blk, GEMM_SMEM>>>(
        o, PP, woR, HID, out, HID, HID, PP, 0, 0);
}

// round 10
// speedup vs baseline: 1.4433x; 1.4433x over previous
#include <cuda_runtime.h>
#include <math.h>
#include <stdint.h>

#define TT   4096
#define HID  2048
#define NH   32
#define HD   128
#define PP   4096
#define TP   (TT * PP)
#define NQKV 12288    // 3*PP
#define NFAB 384      // fa(128) | ga(128) | beta(32 pad->128)

// ---------------- scratch (device globals; no allocations allowed) ----------
__device__ float g_hsr[TT * HID];
__device__ float g_qkvp[TT * NQKV];
__device__ float g_q [TP];
__device__ float g_k [TP];
__device__ float g_v [TP];
__device__ float g_eg[TP];
__device__ float g_g2[TP];
__device__ float g_o [TP];
__device__ float g_fab[TT * NFAB];
__device__ float g_beta[TT * NH];
__device__ float g_wqkvR[HID * NQKV];
__device__ float g_wfabR[HID * NFAB];
__device__ float g_wfbR[HD * PP];
__device__ float g_wgbR[HD * PP];
__device__ float g_woR[PP * HID];

// ---------------- helpers -----------------------------------------------------
__device__ __forceinline__ uint32_t smem_u32(const void* p) {
    uint32_t a;
    asm("{ .reg .u64 t; cvta.to.shared.u64 t, %1; cvt.u32.u64 %0, t; }" : "=r"(a) : "l"(p));
    return a;
}
__device__ __forceinline__ float rna_tf32(float x) {
    uint32_t o, i = __float_as_uint(x);
    asm("cvt.rna.tf32.f32 %0, %1;" : "=r"(o) : "r"(i));
    return __uint_as_float(o);
}
__device__ __forceinline__ void cp_async16(uint32_t dst, const float* src) {
    asm volatile("cp.async.cg.shared.global [%0], [%1], 16;\n"
                 :: "r"(dst), "l"(__cvta_generic_to_global(src)));
}
__device__ __forceinline__ void cp_async4(uint32_t dst, const float* src) {
    asm volatile("cp.async.ca.shared.global [%0], [%1], 4;\n"
                 :: "r"(dst), "l"(__cvta_generic_to_global(src)));
}
__device__ __forceinline__ void cp_commit() { asm volatile("cp.async.commit_group;\n" ::: "memory"); }

#define MMA_TF32(d, a, b)                                                      \
    asm volatile("mma.sync.aligned.m16n8k8.row.col.f32.tf32.tf32.f32 "        \
                 "{%0,%1,%2,%3}, {%4,%5,%6,%7}, {%8,%9}, {%0,%1,%2,%3};"      \
                 : "+f"((d)[0]), "+f"((d)[1]), "+f"((d)[2]), "+f"((d)[3])     \
                 : "r"((a)[0]), "r"((a)[1]), "r"((a)[2]), "r"((a)[3]),        \
                   "r"((b)[0]), "r"((b)[1]))

#define LDSM_X4(r, addr)                                                       \
    asm volatile("ldmatrix.sync.aligned.m8n8.x4.shared.b16 {%0,%1,%2,%3}, [%4];" \
                 : "=r"((r)[0]), "=r"((r)[1]), "=r"((r)[2]), "=r"((r)[3])      \
                 : "r"(addr))

// ---------------- tf32 mma.sync GEMM (R8 exact) --------------------------------
#define BM 128
#define BN 128
#define BK 32
#define ASTR 36
#define BSTR 136
#define A_STAGE (BM * ASTR)
#define B_STAGE (BK * BSTR)
#define STAGE_F (A_STAGE + B_STAGE)
#define NSTAGE 3
#define GEMM_SMEM (NSTAGE * STAGE_F * 4)

__global__ __launch_bounds__(256, 2) void mma_gemm(const float* __restrict__ A, int lda,
                                                   const float* __restrict__ B, int ldb,
                                                   float* __restrict__ C, int ldc,
                                                   int Nvalid, int K, int round_limit) {
    extern __shared__ float sm[];
    const uint32_t sb = smem_u32(sm);

    const int tid = threadIdx.x;
    const int wid = tid >> 5, lane = tid & 31;
    const int g = lane >> 2, tig = lane & 3;
    const int wm = (wid & 1) * 64, wn = (wid >> 1) * 32;
    const int bm = blockIdx.y * BM, bn = blockIdx.x * BN;
    const int NC = K >> 5;

    const int arow = tid >> 3, akq = tid & 7;
    const int brow = tid >> 5, bnq = tid & 31;
    const int aoff = (wm + (lane & 7) + ((lane >> 3) & 1) * 8) * ASTR + (lane >> 4) * 4;

    float acc[4][4][4];
#pragma unroll
    for (int i = 0; i < 4; i++)
#pragma unroll
        for (int j = 0; j < 4; j++)
#pragma unroll
            for (int r = 0; r < 4; r++) acc[i][j][r] = 0.f;

#define LOADST(chunk, stage) do {                                               \
        const int kb = (chunk) * BK;                                            \
        const uint32_t sA = sb + (stage) * STAGE_F * 4;                         \
        const uint32_t sB = sA + A_STAGE * 4;                                   \
        _Pragma("unroll")                                                       \
        for (int j = 0; j < 4; j++) {                                           \
            const int r = arow + 32 * j;                                        \
            cp_async16(sA + (r * ASTR + akq * 4) * 4,                           \
                       A + (size_t)(bm + r) * lda + kb + akq * 4);              \
        }                                                                       \
        _Pragma("unroll")                                                       \
        for (int j = 0; j < 4; j++) {                                           \
            const int r = brow + 8 * j;                                         \
            cp_async16(sB + (r * BSTR + bnq * 4) * 4,                           \
                       B + (size_t)(kb + r) * ldb + bn + bnq * 4);              \
        }                                                                       \
        cp_commit();                                                            \
    } while (0)

    LOADST(0, 0);
    if (NC > 1) LOADST(1, 1);

    for (int i = 0; i < NC; i++) {
        if (i + 2 < NC) asm volatile("cp.async.wait_group 1;\n" ::: "memory");
        else            asm volatile("cp.async.wait_group 0;\n" ::: "memory");
        __syncthreads();
        if (i + 2 < NC) {
            int st = i + 2;
            st = st - (st / NSTAGE) * NSTAGE;
            LOADST(i + 2, st);
        }

        const int stage = i - (i / NSTAGE) * NSTAGE;
        const uint32_t aBase = sb + stage * (STAGE_F * 4);
        const float* bb = sm + stage * STAGE_F + A_STAGE;
#pragma unroll
        for (int s = 0; s < 4; s++) {
            uint32_t af[4][4], bf[4][2];
            const int kk = 8 * s + tig;
#pragma unroll
            for (int mf = 0; mf < 4; mf++)
                LDSM_X4(af[mf], aBase + (uint32_t)(aoff + mf * (16 * ASTR) + 8 * s) * 4);
            const float* brow0 = bb + kk * BSTR + wn;
#pragma unroll
            for (int nf = 0; nf < 4; nf++) {
                bf[nf][0] = __float_as_uint(brow0[8 * nf + g]);
                bf[nf][1] = __float_as_uint(brow0[8 * nf + g + 4 * BSTR]);
            }
#pragma unroll
            for (int mf = 0; mf < 4; mf++)
#pragma unroll
                for (int nf = 0; nf < 4; nf++)
                    MMA_TF32(acc[mf][nf], af[mf], bf[nf]);
        }
    }

#pragma unroll
    for (int mf = 0; mf < 4; mf++) {
        const int row0 = bm + wm + 16 * mf + g;
#pragma unroll
        for (int nf = 0; nf < 4; nf++) {
            const int col = bn + wn + 8 * nf + 2 * tig;
            if (col < Nvalid) {
                float4 vals = make_float4(acc[mf][nf][0], acc[mf][nf][1],
                                          acc[mf][nf][2], acc[mf][nf][3]);
                if (col < round_limit) {
                    vals.x = rna_tf32(vals.x); vals.y = rna_tf32(vals.y);
                    vals.z = rna_tf32(vals.z); vals.w = rna_tf32(vals.w);
                }
                *reinterpret_cast<float2*>(C + (size_t)row0 * ldc + col) =
                    make_float2(vals.x, vals.y);
                *reinterpret_cast<float2*>(C + (size_t)(row0 + 8) * ldc + col) =
                    make_float2(vals.z, vals.w);
            }
        }
    }
}

// ---------------- prep kernels (R8 exact) ---------------------------------------
__global__ void prep_w4(const float4* __restrict__ in, float4* __restrict__ out, int n4) {
    const int i = blockIdx.x * 256 + threadIdx.x;
    if (i >= n4) return;
    float4 v = in[i];
    v.x = rna_tf32(v.x); v.y = rna_tf32(v.y);
    v.z = rna_tf32(v.z); v.w = rna_tf32(v.w);
    out[i] = v;
}

__global__ void prep_wqkv(const float4* __restrict__ wq, const float4* __restrict__ wk,
                          const float4* __restrict__ wv, float4* __restrict__ out, int total4) {
    const int i = blockIdx.x * 256 + threadIdx.x;
    if (i >= total4) return;
    const int n4 = i % (NQKV / 4);
    const int row = i / (NQKV / 4);
    const int seg = n4 >> 10;
    const int off = row * (PP / 4) + (n4 & 1023);
    float4 v = (seg == 0) ? wq[off] : (seg == 1) ? wk[off] : wv[off];
    v.x = rna_tf32(v.x); v.y = rna_tf32(v.y);
    v.z = rna_tf32(v.z); v.w = rna_tf32(v.w);
    out[i] = v;
}

__global__ void prep_wfab(const float4* __restrict__ wfa, const float4* __restrict__ wga,
                          const float4* __restrict__ wb, float4* __restrict__ out, int total4) {
    const int i = blockIdx.x * 256 + threadIdx.x;
    if (i >= total4) return;
    const int n4 = i % (NFAB / 4);
    const int row = i / (NFAB / 4);
    float4 v = make_float4(0.f, 0.f, 0.f, 0.f);
    if (n4 < 32)       v = wfa[row * 32 + n4];
    else if (n4 < 64)  v = wga[row * 32 + (n4 - 32)];
    else if (n4 < 72)  v = wb[row * 8 + (n4 - 64)];
    v.x = rna_tf32(v.x); v.y = rna_tf32(v.y);
    v.z = rna_tf32(v.z); v.w = rna_tf32(v.w);
    out[i] = v;
}

// ---------------- conv / beta / gate (R8 exact) ---------------------------------
__global__ __launch_bounds__(256) void conv_silu_k(const float* __restrict__ x,
                                                   const float* __restrict__ w,
                                                   float* __restrict__ y, float scale) {
    const int idx = blockIdx.x * 256 + threadIdx.x;
    const int t = idx >> 12;
    const int p = idx & (PP - 1);
    const size_t xi = (size_t)t * NQKV + p;
    const float4 wv = *reinterpret_cast<const float4*>(w + p * 4);
    float acc = x[xi] * wv.w;
    if (t >= 1) acc += x[xi - NQKV] * wv.z;
    if (t >= 2) acc += x[xi - 2 * NQKV] * wv.y;
    if (t >= 3) acc += x[xi - 3 * NQKV] * wv.x;
    const float sg = 1.f / (1.f + expf(-acc));
    y[idx] = acc * sg * scale;
}

__global__ void beta_k(const float* __restrict__ fab, float* __restrict__ b) {
    const int idx = blockIdx.x * 256 + threadIdx.x;
    if (idx >= TT * NH) return;
    const int t = idx >> 5, h = idx & 31;
    const float x = fab[(size_t)t * NFAB + 256 + h];
    b[idx] = 2.f / (1.f + expf(-x));
}

__global__ __launch_bounds__(256) void gate_k(float* __restrict__ g,
                                              const float* __restrict__ dt_bias,
                                              const float* __restrict__ A_log) {
    const int idx = blockIdx.x * 256 + threadIdx.x;
    const int p = idx & (PP - 1);
    const int h = p >> 7;
    const float a = expf(A_log[h]);
    const float x = g[idx] + dt_bias[p];
    const float sg = 1.f / (1.f + expf(-a * x));
    g[idx] = expf(-5.f * sg);
}

// ---------------- KDA scan v3: 512 threads, s=16, register prefetch -----------
// CTA = (jblock, head): 32 v-columns x 16 state-threads (8 state els/thread).
#define SBLK 8
#define SLOT_F 420                // k128|q128|e128|v32|beta1|pad3
#define BUF_F (SBLK * SLOT_F)
#define SNBUF 3
#define NBLK (TT / SBLK)

__global__ __launch_bounds__(512) void scan_k(const float* __restrict__ q,
                                              const float* __restrict__ k,
                                              const float* __restrict__ v,
                                              const float* __restrict__ eg,
                                              const float* __restrict__ beta,
                                              float* __restrict__ o) {
    __shared__ float ring[SNBUF * BUF_F];   // 40.3KB

    const int tid = threadIdx.x;
    const int h = blockIdx.y;
    const int jb = blockIdx.x;              // 0..3
    const int jl = tid >> 4;                // column within block (0..31)
    const int s = tid & 15;                 // state slice (0..15), 8 els each
    const int off_v = h * HD + jb * 32 + jl;
    const uint32_t ring_u32 = smem_u32(ring);

    const float* kqe_base[3] = {k + h * HD, q + h * HD, eg + h * HD};

#define SCAN_FILL(blk) do {                                                     \
        const int t0 = (blk) * SBLK;                                            \
        const uint32_t bufb = ring_u32 + ((blk) % SNBUF) * (BUF_F * 4);         \
        for (int u = tid; u < SBLK * 104; u += 512) {                           \
            const int st = u / 104;                                             \
            const int item = u - st * 104;                                      \
            const size_t gbase = (size_t)(t0 + st) * PP;                        \
            const float* src;                                                   \
            if (item < 96) src = kqe_base[item >> 5] + gbase + (item & 31) * 4; \
            else           src = v + gbase + h * HD + jb * 32 + (item - 96) * 4;\
            cp_async16(bufb + (st * SLOT_F + item * 4) * 4, src);               \
        }                                                                       \
        if (tid < SBLK)                                                         \
            cp_async4(bufb + (tid * SLOT_F + 416) * 4,                          \
                      beta + (size_t)(t0 + tid) * NH + h);                      \
        cp_commit();                                                            \
    } while (0)

    // register double-buffer for step operands
    float kf[2][8], qf[2][8], ef[2][8], vt[2], bt[2];

#define LOAD_STEP(buf, si, ph) do {                                             \
        const float* slot = (buf) + (si) * SLOT_F;                              \
        float4 a0 = *reinterpret_cast<const float4*>(slot + s * 8);             \
        float4 a1 = *reinterpret_cast<const float4*>(slot + s * 8 + 4);         \
        float4 b0 = *reinterpret_cast<const float4*>(slot + 128 + s * 8);       \
        float4 b1 = *reinterpret_cast<const float4*>(slot + 128 + s * 8 + 4);   \
        float4 c0 = *reinterpret_cast<const float4*>(slot + 256 + s * 8);       \
        float4 c1 = *reinterpret_cast<const float4*>(slot + 256 + s * 8 + 4);   \
        kf[ph][0]=a0.x; kf[ph][1]=a0.y; kf[ph][2]=a0.z; kf[ph][3]=a0.w;         \
        kf[ph][4]=a1.x; kf[ph][5]=a1.y; kf[ph][6]=a1.z; kf[ph][7]=a1.w;         \
        qf[ph][0]=b0.x; qf[ph][1]=b0.y; qf[ph][2]=b0.z; qf[ph][3]=b0.w;         \
        qf[ph][4]=b1.x; qf[ph][5]=b1.y; qf[ph][6]=b1.z; qf[ph][7]=b1.w;         \
        ef[ph][0]=c0.x; ef[ph][1]=c0.y; ef[ph][2]=c0.z; ef[ph][3]=c0.w;         \
        ef[ph][4]=c1.x; ef[ph][5]=c1.y; ef[ph][6]=c1.z; ef[ph][7]=c1.w;         \
        vt[ph] = slot[384 + jl];                                                \
        bt[ph] = slot[416];                                                     \
    } while (0)

    float S[8];
#pragma unroll
    for (int r = 0; r < 8; r++) S[r] = 0.f;

    SCAN_FILL(0);
    SCAN_FILL(1);

    for (int b = 0; b < NBLK; b++) {
        if (b < NBLK - 1) asm volatile("cp.async.wait_group 1;\n" ::: "memory");
        else              asm volatile("cp.async.wait_group 0;\n" ::: "memory");
        __syncthreads();
        if (b + 2 < NBLK) SCAN_FILL(b + 2);

        const float* buf = ring + (b % SNBUF) * BUF_F;
        LOAD_STEP(buf, 0, 0);
#pragma unroll
        for (int si = 0; si < SBLK; si++) {
            const int ph = si & 1;
            if (si + 1 < SBLK) LOAD_STEP(buf, si + 1, ph ^ 1);

            float p0 = 0.f, p1 = 0.f;
#pragma unroll
            for (int r = 0; r < 8; r += 2) {
                S[r]     *= ef[ph][r];     p0 += S[r]     * kf[ph][r];
                S[r + 1] *= ef[ph][r + 1]; p1 += S[r + 1] * kf[ph][r + 1];
            }
            float part = p0 + p1;
            part += __shfl_xor_sync(0xffffffffu, part, 1);
            part += __shfl_xor_sync(0xffffffffu, part, 2);
            part += __shfl_xor_sync(0xffffffffu, part, 4);
            part += __shfl_xor_sync(0xffffffffu, part, 8);
            const float u = bt[ph] * (vt[ph] - part);
            float o0 = 0.f, o1 = 0.f;
#pragma unroll
            for (int r = 0; r < 8; r += 2) {
                S[r]     += kf[ph][r] * u;     o0 += qf[ph][r]     * S[r];
                S[r + 1] += kf[ph][r + 1] * u; o1 += qf[ph][r + 1] * S[r + 1];
            }
            float po = o0 + o1;
            po += __shfl_xor_sync(0xffffffffu, po, 1);
            po += __shfl_xor_sync(0xffffffffu, po, 2);
            po += __shfl_xor_sync(0xffffffffu, po, 4);
            po += __shfl_xor_sync(0xffffffffu, po, 8);
            if (s == 0) o[(size_t)(b * SBLK + si) * PP + off_v] = po;
        }
        __syncthreads();
    }
}

// ---------------- gated RMSNorm (R8 exact) --------------------------------------
__global__ __launch_bounds__(256) void rmsnorm_k(float* __restrict__ o,
                                                 const float* __restrict__ g2,
                                                 const float* __restrict__ w) {
    const int warp = (blockIdx.x * blockDim.x + threadIdx.x) >> 5;
    const int lane = threadIdx.x & 31;
    if (warp >= TT * NH) return;
    const int base = warp * HD + lane * 4;
    float4 x = *reinterpret_cast<const float4*>(o + base);
    float ss = x.x * x.x + x.y * x.y + x.z * x.z + x.w * x.w;
#pragma unroll
    for (int d = 16; d > 0; d >>= 1) ss += __shfl_xor_sync(0xffffffffu, ss, d);
    const float rstd = rsqrtf(ss * (1.f / 128.f) + 1e-5f);
    const float4 g = *reinterpret_cast<const float4*>(g2 + base);
    const float4 wv = *reinterpret_cast<const float4*>(w + lane * 4);
    float4 r;
    r.x = rna_tf32(x.x * rstd * wv.x / (1.f + expf(-g.x)));
    r.y = rna_tf32(x.y * rstd * wv.y / (1.f + expf(-g.y)));
    r.z = rna_tf32(x.z * rstd * wv.z / (1.f + expf(-g.z)));
    r.w = rna_tf32(x.w * rstd * wv.w / (1.f + expf(-g.w)));
    *reinterpret_cast<float4*>(o + base) = r;
}

// ---------------- launch --------------------------------------------------------
extern "C" void kernel_launch(void* const* d_in, const int* in_sizes, int n_in,
                              void* d_out, int out_size) {
    const float* hs   = (const float*)d_in[0];
    const float* Wq   = (const float*)d_in[1];
    const float* Wk   = (const float*)d_in[2];
    const float* Wv   = (const float*)d_in[3];
    const float* cq   = (const float*)d_in[4];
    const float* ck   = (const float*)d_in[5];
    const float* cv   = (const float*)d_in[6];
    const float* Wb   = (const float*)d_in[7];
    const float* Wfa  = (const float*)d_in[8];
    const float* Wfb  = (const float*)d_in[9];
    const float* dtb  = (const float*)d_in[10];
    const float* Alog = (const float*)d_in[11];
    const float* Wga  = (const float*)d_in[12];
    const float* Wgb  = (const float*)d_in[13];
    const float* onw  = (const float*)d_in[14];
    const float* Wo   = (const float*)d_in[15];
    float* out = (float*)d_out;

    float *hsr, *qkvp, *q, *k, *v, *eg, *g2, *o, *fab, *beta;
    float *wqkvR, *wfabR, *wfbR, *wgbR, *woR;
    cudaGetSymbolAddress((void**)&hsr, g_hsr);
    cudaGetSymbolAddress((void**)&qkvp, g_qkvp);
    cudaGetSymbolAddress((void**)&q,  g_q);
    cudaGetSymbolAddress((void**)&k,  g_k);
    cudaGetSymbolAddress((void**)&v,  g_v);
    cudaGetSymbolAddress((void**)&eg, g_eg);
    cudaGetSymbolAddress((void**)&g2, g_g2);
    cudaGetSymbolAddress((void**)&o,  g_o);
    cudaGetSymbolAddress((void**)&fab, g_fab);
    cudaGetSymbolAddress((void**)&beta, g_beta);
    cudaGetSymbolAddress((void**)&wqkvR, g_wqkvR);
    cudaGetSymbolAddress((void**)&wfabR, g_wfabR);
    cudaGetSymbolAddress((void**)&wfbR, g_wfbR);
    cudaGetSymbolAddress((void**)&wgbR, g_wgbR);
    cudaGetSymbolAddress((void**)&woR, g_woR);

    cudaFuncSetAttribute(mma_gemm, cudaFuncAttributeMaxDynamicSharedMemorySize, GEMM_SMEM);

    const dim3 blk(256);

    // preps
    prep_w4<<<(TT * HID / 4 + 255) / 256, blk>>>((const float4*)hs, (float4*)hsr, TT * HID / 4);
    prep_wqkv<<<(HID * NQKV / 4 + 255) / 256, blk>>>((const float4*)Wq, (const float4*)Wk,
                                                     (const float4*)Wv, (float4*)wqkvR,
                                                     HID * NQKV / 4);
    prep_wfab<<<(HID * NFAB / 4 + 255) / 256, blk>>>((const float4*)Wfa, (const float4*)Wga,
                                                     (const float4*)Wb, (float4*)wfabR,
                                                     HID * NFAB / 4);

    // GEMMs
    mma_gemm<<<dim3(48, 32), blk, GEMM_SMEM>>>(hsr, HID, wqkvR, NQKV, qkvp, NQKV,
                                               NQKV / 2, HID, 0);
    mma_gemm<<<dim3(48, 32), blk, GEMM_SMEM>>>(hsr, HID, wqkvR + NQKV / 2, NQKV,
                                               qkvp + NQKV / 2, NQKV, NQKV / 2, HID, 0);
    mma_gemm<<<dim3(3, 32), blk, GEMM_SMEM>>>(hsr, HID, wfabR, NFAB, fab, NFAB,
                                              288, HID, 256);

    // convs + beta
    conv_silu_k<<<TP / 256, blk>>>(qkvp,          cq, q, 0.08838834764831845f);
    conv_silu_k<<<TP / 256, blk>>>(qkvp + PP,     ck, k, 1.f);
    conv_silu_k<<<TP / 256, blk>>>(qkvp + 2 * PP, cv, v, 1.f);
    beta_k<<<(TT * NH + 255) / 256, blk>>>(fab, beta);

    // gate GEMMs
    prep_w4<<<(HD * PP / 4 + 255) / 256, blk>>>((const float4*)Wfb, (float4*)wfbR, HD * PP / 4);
    mma_gemm<<<dim3(32, 32), blk, GEMM_SMEM>>>(fab, NFAB, wfbR, PP, eg, PP, PP, HD, 0);
    gate_k<<<TP / 256, blk>>>(eg, dtb, Alog);
    prep_w4<<<(HD * PP / 4 + 255) / 256, blk>>>((const float4*)Wgb, (float4*)wgbR, HD * PP / 4);
    mma_gemm<<<dim3(32, 32), blk, GEMM_SMEM>>>(fab + 128, NFAB, wgbR, PP, g2, PP, PP, HD, 0);

    // sequential KDA scan (v3: 512 threads, s=16, register prefetch)
    scan_k<<<dim3(4, NH), 512>>>(q, k, v, eg, beta, o);

    // gated rmsnorm + output projection
    rmsnorm_k<<<(TT * NH * 32) / 256, blk>>>(o, g2, onw);
    prep_w4<<<(PP * HID / 4 + 255) / 256, blk>>>((const float4*)Wo, (float4*)woR, PP * HID / 4);
    mma_gemm<<<dim3(16, 32), blk, GEMM_SMEM>>>(o, PP, woR, HID, out, HID, HID, PP, 0);
}

// round 11
// speedup vs baseline: 1.5122x; 1.0478x over previous
#include <cuda_runtime.h>
#include <math.h>
#include <stdint.h>

#define TT   4096
#define HID  2048
#define NH   32
#define HD   128
#define PP   4096
#define TP   (TT * PP)
#define NQKV 12288    // 3*PP
#define NFAB 384      // fa(128) | ga(128) | beta(32 pad->128)

// ---------------- scratch (device globals; no allocations allowed) ----------
__device__ float g_hsr[TT * HID];
__device__ float g_qkvp[TT * NQKV];
__device__ float g_q [TP];
__device__ float g_k [TP];
__device__ float g_v [TP];
__device__ float g_eg[TP];
__device__ float g_g2[TP];
__device__ float g_o [TP];
__device__ float g_fab[TT * NFAB];
__device__ float g_beta[TT * NH];
__device__ float g_wqkvR[HID * NQKV];
__device__ float g_wfabR[HID * NFAB];
__device__ float g_wfbR[HD * PP];
__device__ float g_wgbR[HD * PP];
__device__ float g_woR[PP * HID];

// ---------------- helpers -----------------------------------------------------
__device__ __forceinline__ uint32_t smem_u32(const void* p) {
    uint32_t a;
    asm("{ .reg .u64 t; cvta.to.shared.u64 t, %1; cvt.u32.u64 %0, t; }" : "=r"(a) : "l"(p));
    return a;
}
__device__ __forceinline__ float rna_tf32(float x) {
    uint32_t o, i = __float_as_uint(x);
    asm("cvt.rna.tf32.f32 %0, %1;" : "=r"(o) : "r"(i));
    return __uint_as_float(o);
}
__device__ __forceinline__ void cp_async16(uint32_t dst, const float* src) {
    asm volatile("cp.async.cg.shared.global [%0], [%1], 16;\n"
                 :: "r"(dst), "l"(__cvta_generic_to_global(src)));
}
__device__ __forceinline__ void cp_async4(uint32_t dst, const float* src) {
    asm volatile("cp.async.ca.shared.global [%0], [%1], 4;\n"
                 :: "r"(dst), "l"(__cvta_generic_to_global(src)));
}
__device__ __forceinline__ void cp_commit() { asm volatile("cp.async.commit_group;\n" ::: "memory"); }

#define MMA_TF32(d, a, b)                                                      \
    asm volatile("mma.sync.aligned.m16n8k8.row.col.f32.tf32.tf32.f32 "        \
                 "{%0,%1,%2,%3}, {%4,%5,%6,%7}, {%8,%9}, {%0,%1,%2,%3};"      \
                 : "+f"((d)[0]), "+f"((d)[1]), "+f"((d)[2]), "+f"((d)[3])     \
                 : "r"((a)[0]), "r"((a)[1]), "r"((a)[2]), "r"((a)[3]),        \
                   "r"((b)[0]), "r"((b)[1]))

#define LDSM_X4(r, addr)                                                       \
    asm volatile("ldmatrix.sync.aligned.m8n8.x4.shared.b16 {%0,%1,%2,%3}, [%4];" \
                 : "=r"((r)[0]), "=r"((r)[1]), "=r"((r)[2]), "=r"((r)[3])      \
                 : "r"(addr))

// ---------------- tf32 mma.sync GEMM (R8/R10 exact) ----------------------------
#define BM 128
#define BN 128
#define BK 32
#define ASTR 36
#define BSTR 136
#define A_STAGE (BM * ASTR)
#define B_STAGE (BK * BSTR)
#define STAGE_F (A_STAGE + B_STAGE)
#define NSTAGE 3
#define GEMM_SMEM (NSTAGE * STAGE_F * 4)

__global__ __launch_bounds__(256, 2) void mma_gemm(const float* __restrict__ A, int lda,
                                                   const float* __restrict__ B, int ldb,
                                                   float* __restrict__ C, int ldc,
                                                   int Nvalid, int K, int round_limit) {
    extern __shared__ float sm[];
    const uint32_t sb = smem_u32(sm);

    const int tid = threadIdx.x;
    const int wid = tid >> 5, lane = tid & 31;
    const int g = lane >> 2, tig = lane & 3;
    const int wm = (wid & 1) * 64, wn = (wid >> 1) * 32;
    const int bm = blockIdx.y * BM, bn = blockIdx.x * BN;
    const int NC = K >> 5;

    const int arow = tid >> 3, akq = tid & 7;
    const int brow = tid >> 5, bnq = tid & 31;
    const int aoff = (wm + (lane & 7) + ((lane >> 3) & 1) * 8) * ASTR + (lane >> 4) * 4;

    float acc[4][4][4];
#pragma unroll
    for (int i = 0; i < 4; i++)
#pragma unroll
        for (int j = 0; j < 4; j++)
#pragma unroll
            for (int r = 0; r < 4; r++) acc[i][j][r] = 0.f;

#define LOADST(chunk, stage) do {                                               \
        const int kb = (chunk) * BK;                                            \
        const uint32_t sA = sb + (stage) * STAGE_F * 4;                         \
        const uint32_t sB = sA + A_STAGE * 4;                                   \
        _Pragma("unroll")                                                       \
        for (int j = 0; j < 4; j++) {                                           \
            const int r = arow + 32 * j;                                        \
            cp_async16(sA + (r * ASTR + akq * 4) * 4,                           \
                       A + (size_t)(bm + r) * lda + kb + akq * 4);              \
        }                                                                       \
        _Pragma("unroll")                                                       \
        for (int j = 0; j < 4; j++) {                                           \
            const int r = brow + 8 * j;                                         \
            cp_async16(sB + (r * BSTR + bnq * 4) * 4,                           \
                       B + (size_t)(kb + r) * ldb + bn + bnq * 4);              \
        }                                                                       \
        cp_commit();                                                            \
    } while (0)

    LOADST(0, 0);
    if (NC > 1) LOADST(1, 1);

    for (int i = 0; i < NC; i++) {
        if (i + 2 < NC) asm volatile("cp.async.wait_group 1;\n" ::: "memory");
        else            asm volatile("cp.async.wait_group 0;\n" ::: "memory");
        __syncthreads();
        if (i + 2 < NC) {
            int st = i + 2;
            st = st - (st / NSTAGE) * NSTAGE;
            LOADST(i + 2, st);
        }

        const int stage = i - (i / NSTAGE) * NSTAGE;
        const uint32_t aBase = sb + stage * (STAGE_F * 4);
        const float* bb = sm + stage * STAGE_F + A_STAGE;
#pragma unroll
        for (int s = 0; s < 4; s++) {
            uint32_t af[4][4], bf[4][2];
            const int kk = 8 * s + tig;
#pragma unroll
            for (int mf = 0; mf < 4; mf++)
                LDSM_X4(af[mf], aBase + (uint32_t)(aoff + mf * (16 * ASTR) + 8 * s) * 4);
            const float* brow0 = bb + kk * BSTR + wn;
#pragma unroll
            for (int nf = 0; nf < 4; nf++) {
                bf[nf][0] = __float_as_uint(brow0[8 * nf + g]);
                bf[nf][1] = __float_as_uint(brow0[8 * nf + g + 4 * BSTR]);
            }
#pragma unroll
            for (int mf = 0; mf < 4; mf++)
#pragma unroll
                for (int nf = 0; nf < 4; nf++)
                    MMA_TF32(acc[mf][nf], af[mf], bf[nf]);
        }
    }

#pragma unroll
    for (int mf = 0; mf < 4; mf++) {
        const int row0 = bm + wm + 16 * mf + g;
#pragma unroll
        for (int nf = 0; nf < 4; nf++) {
            const int col = bn + wn + 8 * nf + 2 * tig;
            if (col < Nvalid) {
                float4 vals = make_float4(acc[mf][nf][0], acc[mf][nf][1],
                                          acc[mf][nf][2], acc[mf][nf][3]);
                if (col < round_limit) {
                    vals.x = rna_tf32(vals.x); vals.y = rna_tf32(vals.y);
                    vals.z = rna_tf32(vals.z); vals.w = rna_tf32(vals.w);
                }
                *reinterpret_cast<float2*>(C + (size_t)row0 * ldc + col) =
                    make_float2(vals.x, vals.y);
                *reinterpret_cast<float2*>(C + (size_t)(row0 + 8) * ldc + col) =
                    make_float2(vals.z, vals.w);
            }
        }
    }
}

// ---------------- prep kernels (R8/R10 exact) -----------------------------------
__global__ void prep_w4(const float4* __restrict__ in, float4* __restrict__ out, int n4) {
    const int i = blockIdx.x * 256 + threadIdx.x;
    if (i >= n4) return;
    float4 v = in[i];
    v.x = rna_tf32(v.x); v.y = rna_tf32(v.y);
    v.z = rna_tf32(v.z); v.w = rna_tf32(v.w);
    out[i] = v;
}

__global__ void prep_wqkv(const float4* __restrict__ wq, const float4* __restrict__ wk,
                          const float4* __restrict__ wv, float4* __restrict__ out, int total4) {
    const int i = blockIdx.x * 256 + threadIdx.x;
    if (i >= total4) return;
    const int n4 = i % (NQKV / 4);
    const int row = i / (NQKV / 4);
    const int seg = n4 >> 10;
    const int off = row * (PP / 4) + (n4 & 1023);
    float4 v = (seg == 0) ? wq[off] : (seg == 1) ? wk[off] : wv[off];
    v.x = rna_tf32(v.x); v.y = rna_tf32(v.y);
    v.z = rna_tf32(v.z); v.w = rna_tf32(v.w);
    out[i] = v;
}

__global__ void prep_wfab(const float4* __restrict__ wfa, const float4* __restrict__ wga,
                          const float4* __restrict__ wb, float4* __restrict__ out, int total4) {
    const int i = blockIdx.x * 256 + threadIdx.x;
    if (i >= total4) return;
    const int n4 = i % (NFAB / 4);
    const int row = i / (NFAB / 4);
    float4 v = make_float4(0.f, 0.f, 0.f, 0.f);
    if (n4 < 32)       v = wfa[row * 32 + n4];
    else if (n4 < 64)  v = wga[row * 32 + (n4 - 32)];
    else if (n4 < 72)  v = wb[row * 8 + (n4 - 64)];
    v.x = rna_tf32(v.x); v.y = rna_tf32(v.y);
    v.z = rna_tf32(v.z); v.w = rna_tf32(v.w);
    out[i] = v;
}

// ---------------- conv / beta / gate (R8/R10 exact) -----------------------------
__global__ __launch_bounds__(256) void conv_silu_k(const float* __restrict__ x,
                                                   const float* __restrict__ w,
                                                   float* __restrict__ y, float scale) {
    const int idx = blockIdx.x * 256 + threadIdx.x;
    const int t = idx >> 12;
    const int p = idx & (PP - 1);
    const size_t xi = (size_t)t * NQKV + p;
    const float4 wv = *reinterpret_cast<const float4*>(w + p * 4);
    float acc = x[xi] * wv.w;
    if (t >= 1) acc += x[xi - NQKV] * wv.z;
    if (t >= 2) acc += x[xi - 2 * NQKV] * wv.y;
    if (t >= 3) acc += x[xi - 3 * NQKV] * wv.x;
    const float sg = 1.f / (1.f + expf(-acc));
    y[idx] = acc * sg * scale;
}

__global__ void beta_k(const float* __restrict__ fab, float* __restrict__ b) {
    const int idx = blockIdx.x * 256 + threadIdx.x;
    if (idx >= TT * NH) return;
    const int t = idx >> 5, h = idx & 31;
    const float x = fab[(size_t)t * NFAB + 256 + h];
    b[idx] = 2.f / (1.f + expf(-x));
}

__global__ __launch_bounds__(256) void gate_k(float* __restrict__ g,
                                              const float* __restrict__ dt_bias,
                                              const float* __restrict__ A_log) {
    const int idx = blockIdx.x * 256 + threadIdx.x;
    const int p = idx & (PP - 1);
    const int h = p >> 7;
    const float a = expf(A_log[h]);
    const float x = g[idx] + dt_bias[p];
    const float sg = 1.f / (1.f + expf(-a * x));
    g[idx] = expf(-5.f * sg);
}

// ---------------- KDA scan v4: 1024 threads, s=32, register prefetch ----------
// CTA = (jblock, head): 32 v-columns x 32 state-threads (4 state els/thread).
#define SBLK 8
#define SLOT_F 420                // k128|q128|e128|v32|beta1|pad3
#define BUF_F (SBLK * SLOT_F)
#define SNBUF 3
#define NBLK (TT / SBLK)

__global__ __launch_bounds__(1024) void scan_k(const float* __restrict__ q,
                                               const float* __restrict__ k,
                                               const float* __restrict__ v,
                                               const float* __restrict__ eg,
                                               const float* __restrict__ beta,
                                               float* __restrict__ o) {
    __shared__ float ring[SNBUF * BUF_F];   // 40.3KB

    const int tid = threadIdx.x;
    const int h = blockIdx.y;
    const int jb = blockIdx.x;              // 0..3
    const int jl = tid >> 5;                // column within block (0..31)
    const int s = tid & 31;                 // state slice (0..31), 4 els each
    const int off_v = h * HD + jb * 32 + jl;
    const uint32_t ring_u32 = smem_u32(ring);

    const float* kqe_base[3] = {k + h * HD, q + h * HD, eg + h * HD};

#define SCAN_FILL(blk) do {                                                     \
        const int t0 = (blk) * SBLK;                                            \
        const uint32_t bufb = ring_u32 + ((blk) % SNBUF) * (BUF_F * 4);         \
        if (tid < SBLK * 104) {                                                 \
            const int st = tid / 104;                                           \
            const int item = tid - st * 104;                                    \
            const size_t gbase = (size_t)(t0 + st) * PP;                        \
            const float* src;                                                   \
            if (item < 96) src = kqe_base[item >> 5] + gbase + (item & 31) * 4; \
            else           src = v + gbase + h * HD + jb * 32 + (item - 96) * 4;\
            cp_async16(bufb + (st * SLOT_F + item * 4) * 4, src);               \
        }                                                                       \
        if (tid < SBLK)                                                         \
            cp_async4(bufb + (tid * SLOT_F + 416) * 4,                          \
                      beta + (size_t)(t0 + tid) * NH + h);                      \
        cp_commit();                                                            \
    } while (0)

    // register double-buffer for step operands (4 state elements per thread)
    float kf[2][4], qf[2][4], ef[2][4], vt[2], bt[2];

#define LOAD_STEP(buf, si, ph) do {                                             \
        const float* slot = (buf) + (si) * SLOT_F;                              \
        float4 a0 = *reinterpret_cast<const float4*>(slot + s * 4);             \
        float4 b0 = *reinterpret_cast<const float4*>(slot + 128 + s * 4);       \
        float4 c0 = *reinterpret_cast<const float4*>(slot + 256 + s * 4);       \
        kf[ph][0]=a0.x; kf[ph][1]=a0.y; kf[ph][2]=a0.z; kf[ph][3]=a0.w;         \
        qf[ph][0]=b0.x; qf[ph][1]=b0.y; qf[ph][2]=b0.z; qf[ph][3]=b0.w;         \
        ef[ph][0]=c0.x; ef[ph][1]=c0.y; ef[ph][2]=c0.z; ef[ph][3]=c0.w;         \
        vt[ph] = slot[384 + jl];                                                \
        bt[ph] = slot[416];                                                     \
    } while (0)

    float S[4];
#pragma unroll
    for (int r = 0; r < 4; r++) S[r] = 0.f;

    SCAN_FILL(0);
    SCAN_FILL(1);

    for (int b = 0; b < NBLK; b++) {
        if (b < NBLK - 1) asm volatile("cp.async.wait_group 1;\n" ::: "memory");
        else              asm volatile("cp.async.wait_group 0;\n" ::: "memory");
        __syncthreads();
        if (b + 2 < NBLK) SCAN_FILL(b + 2);

        const float* buf = ring + (b % SNBUF) * BUF_F;
        LOAD_STEP(buf, 0, 0);
#pragma unroll
        for (int si = 0; si < SBLK; si++) {
            const int ph = si & 1;
            if (si + 1 < SBLK) LOAD_STEP(buf, si + 1, ph ^ 1);

            float p0 = 0.f, p1 = 0.f;
#pragma unroll
            for (int r = 0; r < 4; r += 2) {
                S[r]     *= ef[ph][r];     p0 += S[r]     * kf[ph][r];
                S[r + 1] *= ef[ph][r + 1]; p1 += S[r + 1] * kf[ph][r + 1];
            }
            float part = p0 + p1;
            part += __shfl_xor_sync(0xffffffffu, part, 1);
            part += __shfl_xor_sync(0xffffffffu, part, 2);
            part += __shfl_xor_sync(0xffffffffu, part, 4);
            part += __shfl_xor_sync(0xffffffffu, part, 8);
            part += __shfl_xor_sync(0xffffffffu, part, 16);
            const float u = bt[ph] * (vt[ph] - part);
            float o0 = 0.f, o1 = 0.f;
#pragma unroll
            for (int r = 0; r < 4; r += 2) {
                S[r]     += kf[ph][r] * u;     o0 += qf[ph][r]     * S[r];
                S[r + 1] += kf[ph][r + 1] * u; o1 += qf[ph][r + 1] * S[r + 1];
            }
            float po = o0 + o1;
            po += __shfl_xor_sync(0xffffffffu, po, 1);
            po += __shfl_xor_sync(0xffffffffu, po, 2);
            po += __shfl_xor_sync(0xffffffffu, po, 4);
            po += __shfl_xor_sync(0xffffffffu, po, 8);
            po += __shfl_xor_sync(0xffffffffu, po, 16);
            if (s == 0) o[(size_t)(b * SBLK + si) * PP + off_v] = po;
        }
        __syncthreads();
    }
}

// ---------------- gated RMSNorm (R8/R10 exact) ----------------------------------
__global__ __launch_bounds__(256) void rmsnorm_k(float* __restrict__ o,
                                                 const float* __restrict__ g2,
                                                 const float* __restrict__ w) {
    const int warp = (blockIdx.x * blockDim.x + threadIdx.x) >> 5;
    const int lane = threadIdx.x & 31;
    if (warp >= TT * NH) return;
    const int base = warp * HD + lane * 4;
    float4 x = *reinterpret_cast<const float4*>(o + base);
    float ss = x.x * x.x + x.y * x.y + x.z * x.z + x.w * x.w;
#pragma unroll
    for (int d = 16; d > 0; d >>= 1) ss += __shfl_xor_sync(0xffffffffu, ss, d);
    const float rstd = rsqrtf(ss * (1.f / 128.f) + 1e-5f);
    const float4 g = *reinterpret_cast<const float4*>(g2 + base);
    const float4 wv = *reinterpret_cast<const float4*>(w + lane * 4);
    float4 r;
    r.x = rna_tf32(x.x * rstd * wv.x / (1.f + expf(-g.x)));
    r.y = rna_tf32(x.y * rstd * wv.y / (1.f + expf(-g.y)));
    r.z = rna_tf32(x.z * rstd * wv.z / (1.f + expf(-g.z)));
    r.w = rna_tf32(x.w * rstd * wv.w / (1.f + expf(-g.w)));
    *reinterpret_cast<float4*>(o + base) = r;
}

// ---------------- launch --------------------------------------------------------
extern "C" void kernel_launch(void* const* d_in, const int* in_sizes, int n_in,
                              void* d_out, int out_size) {
    const float* hs   = (const float*)d_in[0];
    const float* Wq   = (const float*)d_in[1];
    const float* Wk   = (const float*)d_in[2];
    const float* Wv   = (const float*)d_in[3];
    const float* cq   = (const float*)d_in[4];
    const float* ck   = (const float*)d_in[5];
    const float* cv   = (const float*)d_in[6];
    const float* Wb   = (const float*)d_in[7];
    const float* Wfa  = (const float*)d_in[8];
    const float* Wfb  = (const float*)d_in[9];
    const float* dtb  = (const float*)d_in[10];
    const float* Alog = (const float*)d_in[11];
    const float* Wga  = (const float*)d_in[12];
    const float* Wgb  = (const float*)d_in[13];
    const float* onw  = (const float*)d_in[14];
    const float* Wo   = (const float*)d_in[15];
    float* out = (float*)d_out;

    float *hsr, *qkvp, *q, *k, *v, *eg, *g2, *o, *fab, *beta;
    float *wqkvR, *wfabR, *wfbR, *wgbR, *woR;
    cudaGetSymbolAddress((void**)&hsr, g_hsr);
    cudaGetSymbolAddress((void**)&qkvp, g_qkvp);
    cudaGetSymbolAddress((void**)&q,  g_q);
    cudaGetSymbolAddress((void**)&k,  g_k);
    cudaGetSymbolAddress((void**)&v,  g_v);
    cudaGetSymbolAddress((void**)&eg, g_eg);
    cudaGetSymbolAddress((void**)&g2, g_g2);
    cudaGetSymbolAddress((void**)&o,  g_o);
    cudaGetSymbolAddress((void**)&fab, g_fab);
    cudaGetSymbolAddress((void**)&beta, g_beta);
    cudaGetSymbolAddress((void**)&wqkvR, g_wqkvR);
    cudaGetSymbolAddress((void**)&wfabR, g_wfabR);
    cudaGetSymbolAddress((void**)&wfbR, g_wfbR);
    cudaGetSymbolAddress((void**)&wgbR, g_wgbR);
    cudaGetSymbolAddress((void**)&woR, g_woR);

    cudaFuncSetAttribute(mma_gemm, cudaFuncAttributeMaxDynamicSharedMemorySize, GEMM_SMEM);

    const dim3 blk(256);

    // preps
    prep_w4<<<(TT * HID / 4 + 255) / 256, blk>>>((const float4*)hs, (float4*)hsr, TT * HID / 4);
    prep_wqkv<<<(HID * NQKV / 4 + 255) / 256, blk>>>((const float4*)Wq, (const float4*)Wk,
                                                     (const float4*)Wv, (float4*)wqkvR,
                                                     HID * NQKV / 4);
    prep_wfab<<<(HID * NFAB / 4 + 255) / 256, blk>>>((const float4*)Wfa, (const float4*)Wga,
                                                     (const float4*)Wb, (float4*)wfabR,
                                                     HID * NFAB / 4);

    // GEMMs
    mma_gemm<<<dim3(48, 32), blk, GEMM_SMEM>>>(hsr, HID, wqkvR, NQKV, qkvp, NQKV,
                                               NQKV / 2, HID, 0);
    mma_gemm<<<dim3(48, 32), blk, GEMM_SMEM>>>(hsr, HID, wqkvR + NQKV / 2, NQKV,
                                               qkvp + NQKV / 2, NQKV, NQKV / 2, HID, 0);
    mma_gemm<<<dim3(3, 32), blk, GEMM_SMEM>>>(hsr, HID, wfabR, NFAB, fab, NFAB,
                                              288, HID, 256);

    // convs + beta
    conv_silu_k<<<TP / 256, blk>>>(qkvp,          cq, q, 0.08838834764831845f);
    conv_silu_k<<<TP / 256, blk>>>(qkvp + PP,     ck, k, 1.f);
    conv_silu_k<<<TP / 256, blk>>>(qkvp + 2 * PP, cv, v, 1.f);
    beta_k<<<(TT * NH + 255) / 256, blk>>>(fab, beta);

    // gate GEMMs
    prep_w4<<<(HD * PP / 4 + 255) / 256, blk>>>((const float4*)Wfb, (float4*)wfbR, HD * PP / 4);
    mma_gemm<<<dim3(32, 32), blk, GEMM_SMEM>>>(fab, NFAB, wfbR, PP, eg, PP, PP, HD, 0);
    gate_k<<<TP / 256, blk>>>(eg, dtb, Alog);
    prep_w4<<<(HD * PP / 4 + 255) / 256, blk>>>((const float4*)Wgb, (float4*)wgbR, HD * PP / 4);
    mma_gemm<<<dim3(32, 32), blk, GEMM_SMEM>>>(fab + 128, NFAB, wgbR, PP, g2, PP, PP, HD, 0);

    // sequential KDA scan (v4: 1024 threads, s=32, register prefetch)
    scan_k<<<dim3(4, NH), 1024>>>(q, k, v, eg, beta, o);

    // gated rmsnorm + output projection
    rmsnorm_k<<<(TT * NH * 32) / 256, blk>>>(o, g2, onw);
    prep_w4<<<(PP * HID / 4 + 255) / 256, blk>>>((const float4*)Wo, (float4*)woR, PP * HID / 4);
    mma_gemm<<<dim3(16, 32), blk, GEMM_SMEM>>>(o, PP, woR, HID, out, HID, HID, PP, 0);
}